// round 6
// baseline (speedup 1.0000x reference)
#include <cuda_runtime.h>
#include <cuda_fp16.h>

#define NMAX  100000
#define EMAX  3200000
#define INF   128
#define HID   50
#define PITCH 64
#define KC    16

// ---------------- static device scratch ----------------
__device__ int    g_is64;
__device__ int    g_cursor;
__device__ int    g_cnt[NMAX];
__device__ int    g_off[NMAX];
__device__ int    g_wcur[NMAX];
__device__ int    g_csrc[EMAX];
__device__ float  g_dinv[NMAX];
__device__ __align__(128) __half g_h1h[(size_t)NMAX * PITCH]; // h1' = dinv*(x@W1)
__device__ float2 g_z[NMAX];                                  // z' = dinv*(h@W2)

// ---------------- dtype sniff + cursor reset ----------------
__global__ void k_sniff(const unsigned int* __restrict__ p) {
    __shared__ int nz;
    int t = threadIdx.x;
    if (t == 0) { nz = 0; g_cursor = 0; }
    __syncthreads();
    if (p[2 * t + 1] != 0u) atomicOr(&nz, 1);
    __syncthreads();
    if (t == 0) g_is64 = nz ? 0 : 1;
}

// ---------------- count degrees (dst half only), 4 edges/thread -------------
__global__ void k_prep(const void* __restrict__ eiv, int E) {
    int i = (blockIdx.x * blockDim.x + threadIdx.x) * 4;
    if (i >= E) return;
    if (!g_is64 && i + 4 <= E) {
        int4 d = *(const int4*)((const int*)eiv + (size_t)E + i);
        atomicAdd(&g_cnt[d.x], 1);
        atomicAdd(&g_cnt[d.y], 1);
        atomicAdd(&g_cnt[d.z], 1);
        atomicAdd(&g_cnt[d.w], 1);
    } else {
        for (int j = i; j < E && j < i + 4; j++) {
            int d;
            if (g_is64) d = (int)((const long long*)eiv)[(size_t)E + j];
            else        d = ((const int*)eiv)[(size_t)E + j];
            atomicAdd(&g_cnt[d], 1);
        }
    }
}

// ---------------- region alloc: warp scan + one atomic per warp --------------
__global__ void k_alloc(int N) {
    int i = blockIdx.x * blockDim.x + threadIdx.x;
    int lane = threadIdx.x & 31;
    int c = (i < N) ? g_cnt[i] : 0;
    int x = c;
#pragma unroll
    for (int o = 1; o < 32; o <<= 1) {
        int y = __shfl_up_sync(0xffffffffu, x, o);
        if (lane >= o) x += y;
    }
    int total = __shfl_sync(0xffffffffu, x, 31);
    int base = 0;
    if (lane == 31 && total > 0) base = atomicAdd(&g_cursor, total);
    base = __shfl_sync(0xffffffffu, base, 31);
    if (i < N) {
        int off = base + x - c;
        g_off[i]  = off;
        g_wcur[i] = off;
        g_dinv[i] = rsqrtf((float)(c + 1));
    }
}

// ---------------- CSR fill, 4 edges/thread ----------------
__global__ void k_fill(const void* __restrict__ eiv, int E) {
    int i = (blockIdx.x * blockDim.x + threadIdx.x) * 4;
    if (i >= E) return;
    if (!g_is64 && i + 4 <= E) {
        const int* p = (const int*)eiv;
        int4 s = *(const int4*)(p + i);
        int4 d = *(const int4*)(p + (size_t)E + i);
        g_csrc[atomicAdd(&g_wcur[d.x], 1)] = s.x;
        g_csrc[atomicAdd(&g_wcur[d.y], 1)] = s.y;
        g_csrc[atomicAdd(&g_wcur[d.z], 1)] = s.z;
        g_csrc[atomicAdd(&g_wcur[d.w], 1)] = s.w;
    } else {
        for (int j = i; j < E && j < i + 4; j++) {
            int s, d;
            if (g_is64) {
                const long long* p = (const long long*)eiv;
                s = (int)p[j];
                d = (int)p[(size_t)E + j];
            } else {
                const int* p = (const int*)eiv;
                s = p[j];
                d = p[(size_t)E + j];
            }
            g_csrc[atomicAdd(&g_wcur[d], 1)] = s;
        }
    }
}

// ---------------- GEMM1: h1' = dinv * (x @ W1), fp16 -------------------------
__global__ void k_gemm1(const float* __restrict__ x, const float* __restrict__ W1, int N) {
    __shared__ float xs[128][KC + 1];
    __shared__ float Ws[KC][52];
    int tid   = threadIdx.x;
    int node0 = blockIdx.x * 128;
    int jg = tid & 3;
    int ng = tid >> 2;

    float acc[4][13];
#pragma unroll
    for (int m = 0; m < 4; m++)
#pragma unroll
        for (int jj = 0; jj < 13; jj++) acc[m][jj] = 0.f;

    for (int k0 = 0; k0 < INF; k0 += KC) {
        for (int i = tid; i < KC * 52; i += 128) {
            int kk = i / 52, j = i % 52;
            Ws[kk][j] = (j < HID) ? W1[(k0 + kk) * HID + j] : 0.f;
        }
#pragma unroll
        for (int r = 0; r < 4; r++) {
            int idx = tid + r * 128;
            int row = idx >> 2, c4 = idx & 3;
            int node = node0 + row;
            float4 v = make_float4(0.f, 0.f, 0.f, 0.f);
            if (node < N)
                v = *(const float4*)(x + (size_t)node * INF + k0 + c4 * 4);
            xs[row][c4 * 4 + 0] = v.x;
            xs[row][c4 * 4 + 1] = v.y;
            xs[row][c4 * 4 + 2] = v.z;
            xs[row][c4 * 4 + 3] = v.w;
        }
        __syncthreads();
#pragma unroll
        for (int kk = 0; kk < KC; kk++) {
            float xm[4];
#pragma unroll
            for (int m = 0; m < 4; m++) xm[m] = xs[ng * 4 + m][kk];
            float wv[13];
#pragma unroll
            for (int jj = 0; jj < 13; jj++) wv[jj] = Ws[kk][jg * 13 + jj];
#pragma unroll
            for (int m = 0; m < 4; m++)
#pragma unroll
                for (int jj = 0; jj < 13; jj++) acc[m][jj] += xm[m] * wv[jj];
        }
        __syncthreads();
    }
#pragma unroll
    for (int m = 0; m < 4; m++) {
        int node = node0 + ng * 4 + m;
        if (node < N) {
            float di = g_dinv[node];
#pragma unroll
            for (int jj = 0; jj < 13; jj++)
                g_h1h[(size_t)node * PITCH + jg * 13 + jj] = __float2half(acc[m][jj] * di);
        }
    }
}

// ---------------- layer-1 agg: int4 idx loads, MLP 8 -------------------------
__global__ void k_agg1(const float* __restrict__ b1, const float* __restrict__ W2, int N) {
    int gt = blockIdx.x * blockDim.x + threadIdx.x;
    int i = gt >> 5, lane = gt & 31;
    if (i >= N) return;

    float dii = g_dinv[i];
    int beg = g_off[i];
    int end = beg + g_cnt[i];

    bool act = lane < 25;
    int  f   = lane * 2;
    const __half* hbase = g_h1h;
    float ax = 0.f, ay = 0.f;
    if (act) {
        float2 v = __half22float2(*(const __half2*)(hbase + ((size_t)i << 6) + f));
        ax = v.x; ay = v.y;                 // self term h1'[i]
    }
    int e = beg;
    // align to 4
    int head = (4 - (beg & 3)) & 3;
    for (int j = 0; j < head && e < end; j++, e++) {
        int s0 = g_csrc[e];
        if (act) {
            float2 v0 = __half22float2(*(const __half2*)(hbase + ((size_t)s0 << 6) + f));
            ax += v0.x; ay += v0.y;
        }
    }
    for (; e + 8 <= end; e += 8) {
        int4 a = *(const int4*)(g_csrc + e);
        int4 b = *(const int4*)(g_csrc + e + 4);
        if (act) {
            float2 v0 = __half22float2(*(const __half2*)(hbase + ((size_t)a.x << 6) + f));
            float2 v1 = __half22float2(*(const __half2*)(hbase + ((size_t)a.y << 6) + f));
            float2 v2 = __half22float2(*(const __half2*)(hbase + ((size_t)a.z << 6) + f));
            float2 v3 = __half22float2(*(const __half2*)(hbase + ((size_t)a.w << 6) + f));
            float2 v4 = __half22float2(*(const __half2*)(hbase + ((size_t)b.x << 6) + f));
            float2 v5 = __half22float2(*(const __half2*)(hbase + ((size_t)b.y << 6) + f));
            float2 v6 = __half22float2(*(const __half2*)(hbase + ((size_t)b.z << 6) + f));
            float2 v7 = __half22float2(*(const __half2*)(hbase + ((size_t)b.w << 6) + f));
            ax += ((v0.x + v1.x) + (v2.x + v3.x)) + ((v4.x + v5.x) + (v6.x + v7.x));
            ay += ((v0.y + v1.y) + (v2.y + v3.y)) + ((v4.y + v5.y) + (v6.y + v7.y));
        }
    }
    for (; e < end; e++) {
        int s0 = g_csrc[e];
        if (act) {
            float2 v0 = __half22float2(*(const __half2*)(hbase + ((size_t)s0 << 6) + f));
            ax += v0.x; ay += v0.y;
        }
    }
    float z0 = 0.f, z1 = 0.f;
    if (act) {
        float2 bb = *(const float2*)(b1 + f);
        float hx = fmaxf(fmaf(ax, dii, bb.x), 0.f);
        float hy = fmaxf(fmaf(ay, dii, bb.y), 0.f);
        float4 w = *(const float4*)(W2 + 2 * f);
        z0 = hx * w.x + hy * w.z;
        z1 = hx * w.y + hy * w.w;
    }
#pragma unroll
    for (int o = 16; o; o >>= 1) {
        z0 += __shfl_xor_sync(0xffffffffu, z0, o);
        z1 += __shfl_xor_sync(0xffffffffu, z1, o);
    }
    if (lane == 0) g_z[i] = make_float2(z0 * dii, z1 * dii);
}

// ---------------- layer-2 agg + log_softmax ----------------------------------
__global__ void k_agg2(const float* __restrict__ b2, float* __restrict__ out, int N) {
    int gt = blockIdx.x * blockDim.x + threadIdx.x;
    int i = gt >> 5, lane = gt & 31;
    if (i >= N) return;

    int beg = g_off[i];
    int end = beg + g_cnt[i];
    float a0 = 0.f, a1 = 0.f;
    for (int e = beg + lane; e < end; e += 32) {
        float2 zv = g_z[g_csrc[e]];
        a0 += zv.x;
        a1 += zv.y;
    }
#pragma unroll
    for (int o = 16; o; o >>= 1) {
        a0 += __shfl_xor_sync(0xffffffffu, a0, o);
        a1 += __shfl_xor_sync(0xffffffffu, a1, o);
    }
    if (lane == 0) {
        float dii = g_dinv[i];
        float2 zi = g_z[i];
        float o0 = fmaf(a0 + zi.x, dii, b2[0]);
        float o1 = fmaf(a1 + zi.y, dii, b2[1]);
        float m   = fmaxf(o0, o1);
        float lse = m + log1pf(expf(fminf(o0, o1) - m));
        out[2 * i + 0] = o0 - lse;
        out[2 * i + 1] = o1 - lse;
    }
}

// ---------------- launch ----------------
extern "C" void kernel_launch(void* const* d_in, const int* in_sizes, int n_in,
                              void* d_out, int out_size) {
    const float* x  = (const float*)d_in[0];
    const void*  ei = (const void*)d_in[1];
    const float* W1 = (const float*)d_in[2];
    const float* b1 = (const float*)d_in[3];
    const float* W2 = (const float*)d_in[4];
    const float* b2 = (const float*)d_in[5];
    float*       out = (float*)d_out;

    int N = in_sizes[0] / INF;
    int E = in_sizes[1] / 2;
    if (N > NMAX) N = NMAX;
    if (E > EMAX) E = EMAX;

    static cudaStream_t sG = (cudaStream_t)0;
    static cudaEvent_t  evA = (cudaEvent_t)0, evB = (cudaEvent_t)0;
    static void* p_cnt = 0;
    static int   inited = 0;
    if (!inited) {
        cudaGetSymbolAddress(&p_cnt, g_cnt);
        if (cudaStreamCreateWithFlags(&sG, cudaStreamNonBlocking) != cudaSuccess) sG = 0;
        if (sG) {
            cudaEventCreateWithFlags(&evA, cudaEventDisableTiming);
            cudaEventCreateWithFlags(&evB, cudaEventDisableTiming);
        }
        inited = 1;
    }
    bool fork = (sG != 0);

    int e4blocks = (E / 4 + 255) / 256 + 1;
    k_sniff<<<1, 256>>>((const unsigned int*)ei);
    cudaMemsetAsync(p_cnt, 0, (size_t)N * sizeof(int), 0);
    k_prep<<<e4blocks, 256>>>(ei, E);
    k_alloc<<<(N + 255) / 256, 256>>>(N);

    if (fork) {
        cudaEventRecord(evA, 0);
        cudaStreamWaitEvent(sG, evA, 0);
        k_gemm1<<<(N + 127) / 128, 128, 0, sG>>>(x, W1, N);   // overlaps k_fill
        cudaEventRecord(evB, sG);
    }

    k_fill<<<e4blocks, 256>>>(ei, E);

    if (fork) {
        cudaStreamWaitEvent(0, evB, 0);
    } else {
        k_gemm1<<<(N + 127) / 128, 128>>>(x, W1, N);
    }

    int agg_blocks = (N * 32 + 255) / 256;
    k_agg1<<<agg_blocks, 256>>>(b1, W2, N);
    k_agg2<<<agg_blocks, 256>>>(b2, out, N);
}